// round 1
// baseline (speedup 1.0000x reference)
#include <cuda_runtime.h>
#include <math.h>

// Problem constants (fixed by the dataset)
#define NN   100000
#define EE   1600000
#define FIN  128
#define HID  64
#define CLS  16

// ---------------- scratch (static __device__ allocations, ~90MB) ------------
__device__ int   g_deg[NN];
__device__ float g_dinv[NN];
__device__ float g_h1s[(size_t)NN * HID];   // h1 * dinv (message source, read-only in scatter)
__device__ float g_acc1[(size_t)NN * HID];  // scatter accumulator (zeroed each call)
__device__ float g_out1[(size_t)NN * HID];  // relu output of layer 1
__device__ float g_h2s[(size_t)NN * CLS];   // h2 * dinv
__device__ float g_acc2[(size_t)NN * CLS];

// ---------------- zero kernels ----------------------------------------------
__global__ void k_zero_deg(int n) {
    int i = blockIdx.x * blockDim.x + threadIdx.x;
    if (i < n) g_deg[i] = 0;
}

__global__ void k_zero_f4(float* __restrict__ p, int n4) {
    int i = blockIdx.x * blockDim.x + threadIdx.x;
    if (i < n4) {
        float4 z = make_float4(0.f, 0.f, 0.f, 0.f);
        ((float4*)p)[i] = z;
    }
}

// ---------------- degree + dinv ---------------------------------------------
__global__ void k_deg(const int* __restrict__ dst, int E) {
    int e = blockIdx.x * blockDim.x + threadIdx.x;
    if (e < E) atomicAdd(&g_deg[dst[e]], 1);
}

__global__ void k_dinv(int N) {
    int i = blockIdx.x * blockDim.x + threadIdx.x;
    if (i < N) g_dinv[i] = rsqrtf((float)g_deg[i] + 1.0f);
}

// ---------------- GEMM1: h1s = (x @ W1) * dinv  -----------------------------
// block (32,8): 32 nodes, each thread computes 8 output features.
__global__ __launch_bounds__(256) void k_gemm1(const float* __restrict__ x,
                                               const float* __restrict__ W1, int N) {
    __shared__ float Ws[FIN * HID];       // 32 KB, same layout as W1
    __shared__ float xs[32][FIN + 1];     // pad to kill bank conflicts

    const int tx = threadIdx.x;           // 0..31 -> node within tile
    const int ty = threadIdx.y;           // 0..7  -> feature group
    const int t  = ty * 32 + tx;
    const int node0 = blockIdx.x * 32;

    #pragma unroll
    for (int i = t; i < FIN * HID; i += 256) Ws[i] = W1[i];
    for (int i = t; i < 32 * FIN; i += 256) {
        int r = i >> 7, c = i & 127;
        int node = node0 + r;
        xs[r][c] = (node < N) ? x[(size_t)node * FIN + c] : 0.f;
    }
    __syncthreads();

    float acc[8];
    #pragma unroll
    for (int j = 0; j < 8; j++) acc[j] = 0.f;
    const int jb = ty * 8;

    #pragma unroll 8
    for (int k = 0; k < FIN; k++) {
        float xv = xs[tx][k];
        #pragma unroll
        for (int j = 0; j < 8; j++) acc[j] += xv * Ws[k * HID + jb + j];
    }

    int node = node0 + tx;
    if (node < N) {
        float d = g_dinv[node];
        float* o = g_h1s + (size_t)node * HID + jb;
        #pragma unroll
        for (int j = 0; j < 8; j++) o[j] = acc[j] * d;
    }
}

// ---------------- scatter layer 1: acc1[dst] += h1s[src] --------------------
// 16 threads per edge, each thread moves one float4 (4 feats).
__global__ __launch_bounds__(256) void k_scatter1(const int* __restrict__ src,
                                                  const int* __restrict__ dst, int E) {
    int u = blockIdx.x * blockDim.x + threadIdx.x;
    if (u >= E * 16) return;
    int e = u >> 4;
    int c = u & 15;
    int s = src[e];
    int d = dst[e];
    float4 v = ((const float4*)(g_h1s + (size_t)s * HID))[c];
    float* p = g_acc1 + (size_t)d * HID + c * 4;
    asm volatile("red.global.add.v4.f32 [%0], {%1,%2,%3,%4};"
                 :: "l"(p), "f"(v.x), "f"(v.y), "f"(v.z), "f"(v.w) : "memory");
}

// ---------------- combine 1: out1 = relu(dinv*(acc1 + h1s) + b1) ------------
__global__ void k_combine1(const float* __restrict__ b1, int N) {
    int u = blockIdx.x * blockDim.x + threadIdx.x;      // over N*HID/4
    if (u >= N * (HID / 4)) return;
    int node = u >> 4;
    int c = u & 15;
    float d = g_dinv[node];
    float4 a  = ((const float4*)g_acc1)[u];
    float4 h  = ((const float4*)g_h1s)[u];
    float4 bb = ((const float4*)b1)[c];
    float4 o;
    o.x = fmaxf(fmaf(d, a.x + h.x, bb.x), 0.f);
    o.y = fmaxf(fmaf(d, a.y + h.y, bb.y), 0.f);
    o.z = fmaxf(fmaf(d, a.z + h.z, bb.z), 0.f);
    o.w = fmaxf(fmaf(d, a.w + h.w, bb.w), 0.f);
    ((float4*)g_out1)[u] = o;
}

// ---------------- GEMM2: h2s = (out1 @ W2) * dinv ---------------------------
// block (32,4): 32 nodes, each thread computes 4 of 16 outputs.
__global__ __launch_bounds__(128) void k_gemm2(const float* __restrict__ W2, int N) {
    __shared__ float Ws[HID * CLS];       // 4 KB
    __shared__ float xs[32][HID + 1];     // 8.3 KB

    const int tx = threadIdx.x;
    const int ty = threadIdx.y;           // 0..3
    const int t  = ty * 32 + tx;
    const int node0 = blockIdx.x * 32;

    for (int i = t; i < HID * CLS; i += 128) Ws[i] = W2[i];
    for (int i = t; i < 32 * HID; i += 128) {
        int r = i >> 6, c = i & 63;
        int node = node0 + r;
        xs[r][c] = (node < N) ? g_out1[(size_t)node * HID + c] : 0.f;
    }
    __syncthreads();

    float acc[4] = {0.f, 0.f, 0.f, 0.f};
    const int jb = ty * 4;

    #pragma unroll 8
    for (int k = 0; k < HID; k++) {
        float xv = xs[tx][k];
        #pragma unroll
        for (int j = 0; j < 4; j++) acc[j] += xv * Ws[k * CLS + jb + j];
    }

    int node = node0 + tx;
    if (node < N) {
        float d = g_dinv[node];
        float* o = g_h2s + (size_t)node * CLS + jb;
        #pragma unroll
        for (int j = 0; j < 4; j++) o[j] = acc[j] * d;
    }
}

// ---------------- scatter layer 2: acc2[dst] += h2s[src] --------------------
// 4 threads per edge, one float4 each.
__global__ __launch_bounds__(256) void k_scatter2(const int* __restrict__ src,
                                                  const int* __restrict__ dst, int E) {
    int u = blockIdx.x * blockDim.x + threadIdx.x;
    if (u >= E * 4) return;
    int e = u >> 2;
    int c = u & 3;
    int s = src[e];
    int d = dst[e];
    float4 v = ((const float4*)(g_h2s + (size_t)s * CLS))[c];
    float* p = g_acc2 + (size_t)d * CLS + c * 4;
    asm volatile("red.global.add.v4.f32 [%0], {%1,%2,%3,%4};"
                 :: "l"(p), "f"(v.x), "f"(v.y), "f"(v.z), "f"(v.w) : "memory");
}

// ---------------- combine 2 + log_softmax -----------------------------------
__global__ void k_logits(const float* __restrict__ b2, float* __restrict__ out, int N) {
    int i = blockIdx.x * blockDim.x + threadIdx.x;
    if (i >= N) return;
    float d = g_dinv[i];
    float z[CLS];
    #pragma unroll
    for (int c = 0; c < 4; c++) {
        float4 a = ((const float4*)g_acc2)[i * 4 + c];
        float4 h = ((const float4*)g_h2s)[i * 4 + c];
        z[c * 4 + 0] = fmaxf(fmaf(d, a.x + h.x, b2[c * 4 + 0]), 0.f);
        z[c * 4 + 1] = fmaxf(fmaf(d, a.y + h.y, b2[c * 4 + 1]), 0.f);
        z[c * 4 + 2] = fmaxf(fmaf(d, a.z + h.z, b2[c * 4 + 2]), 0.f);
        z[c * 4 + 3] = fmaxf(fmaf(d, a.w + h.w, b2[c * 4 + 3]), 0.f);
    }
    float m = z[0];
    #pragma unroll
    for (int j = 1; j < CLS; j++) m = fmaxf(m, z[j]);
    float s = 0.f;
    #pragma unroll
    for (int j = 0; j < CLS; j++) s += expf(z[j] - m);
    float ls = m + logf(s);
    float* o = out + (size_t)i * CLS;
    #pragma unroll
    for (int j = 0; j < CLS; j++) o[j] = z[j] - ls;
}

// ---------------- launcher ---------------------------------------------------
extern "C" void kernel_launch(void* const* d_in, const int* in_sizes, int n_in,
                              void* d_out, int out_size) {
    const float* x  = (const float*)d_in[0];
    const int*   ei = (const int*)d_in[1];
    const float* W1 = (const float*)d_in[2];
    const float* b1 = (const float*)d_in[3];
    const float* W2 = (const float*)d_in[4];
    const float* b2 = (const float*)d_in[5];
    float* out = (float*)d_out;

    const int N = in_sizes[0] / FIN;       // 100000
    const int E = in_sizes[1] / 2;         // 1600000
    const int* src = ei;
    const int* dst = ei + E;

    // Resolve device-symbol addresses for the zero kernel (host side, no alloc)
    // (we just pass raw pointers via cudaGetSymbolAddress-free path: use kernels
    //  that reference the symbols directly, plus generic zero over them)
    // zero deg / acc1 / acc2
    k_zero_deg<<<(N + 255) / 256, 256>>>(N);
    {
        // acc1: N*HID floats -> N*HID/4 float4
        float* acc1p; cudaGetSymbolAddress((void**)&acc1p, g_acc1);
        float* acc2p; cudaGetSymbolAddress((void**)&acc2p, g_acc2);
        int n4a = N * (HID / 4);
        int n4b = N * (CLS / 4);
        k_zero_f4<<<(n4a + 255) / 256, 256>>>(acc1p, n4a);
        k_zero_f4<<<(n4b + 255) / 256, 256>>>(acc2p, n4b);
    }

    k_deg<<<(E + 255) / 256, 256>>>(dst, E);
    k_dinv<<<(N + 255) / 256, 256>>>(N);

    dim3 g1((N + 31) / 32), b1d(32, 8);
    k_gemm1<<<g1, b1d>>>(x, W1, N);

    {
        long long units = (long long)E * 16;
        k_scatter1<<<(unsigned)((units + 255) / 256), 256>>>(src, dst, E);
    }

    {
        int n4 = N * (HID / 4);
        k_combine1<<<(n4 + 255) / 256, 256>>>(b1, N);
    }

    dim3 g2((N + 31) / 32), b2d(32, 4);
    k_gemm2<<<g2, b2d>>>(W2, N);

    {
        long long units = (long long)E * 4;
        k_scatter2<<<(unsigned)((units + 255) / 256), 256>>>(src, dst, E);
    }

    k_logits<<<(N + 255) / 256, 256>>>(b2, out, N);
}

// round 2
// speedup vs baseline: 1.0924x; 1.0924x over previous
#include <cuda_runtime.h>
#include <math.h>

#define NN   100000
#define EE   1600000
#define FIN  128
#define HID  64
#define CLS  16
#define NB_SCAN ((NN + 1023) / 1024)

// ---------------- scratch (static __device__ allocations) -------------------
__device__ int   g_deg[NN];
__device__ int   g_rowstart[NN + 1];
__device__ int   g_cursor[NN];
__device__ int   g_srcsorted[EE];
__device__ int   g_blocksum[256];
__device__ float g_dinv[NN];
__device__ float g_h1s[(size_t)NN * HID];   // (x@W1) * dinv
__device__ float g_out1[(size_t)NN * HID];  // relu layer-1 output
__device__ float g_h2s[(size_t)NN * CLS];   // (out1@W2) * dinv

// ---------------- degree + dinv ---------------------------------------------
__global__ void k_zero_deg(int n) {
    int i = blockIdx.x * blockDim.x + threadIdx.x;
    if (i < n) g_deg[i] = 0;
}

__global__ void k_deg(const int* __restrict__ dst, int E) {
    int e = blockIdx.x * blockDim.x + threadIdx.x;
    if (e < E) atomicAdd(&g_deg[dst[e]], 1);
}

__global__ void k_dinv(int N) {
    int i = blockIdx.x * blockDim.x + threadIdx.x;
    if (i < N) g_dinv[i] = rsqrtf((float)g_deg[i] + 1.0f);
}

// ---------------- CSR build: scan of degrees --------------------------------
__global__ __launch_bounds__(1024) void k_scanA(int N) {
    __shared__ int sh[1024];
    int i = blockIdx.x * 1024 + threadIdx.x;
    sh[threadIdx.x] = (i < N) ? g_deg[i] : 0;
    __syncthreads();
    #pragma unroll
    for (int off = 512; off; off >>= 1) {
        if (threadIdx.x < off) sh[threadIdx.x] += sh[threadIdx.x + off];
        __syncthreads();
    }
    if (threadIdx.x == 0) g_blocksum[blockIdx.x] = sh[0];
}

__global__ void k_scanB(int nb) {
    if (threadIdx.x == 0) {
        int run = 0;
        for (int i = 0; i < nb; i++) { int v = g_blocksum[i]; g_blocksum[i] = run; run += v; }
    }
}

__global__ __launch_bounds__(1024) void k_scanC(int N, int E) {
    __shared__ int sh[1024];
    int i = blockIdx.x * 1024 + threadIdx.x;
    int v = (i < N) ? g_deg[i] : 0;
    sh[threadIdx.x] = v;
    __syncthreads();
    #pragma unroll
    for (int off = 1; off < 1024; off <<= 1) {
        int x = (threadIdx.x >= off) ? sh[threadIdx.x - off] : 0;
        __syncthreads();
        sh[threadIdx.x] += x;
        __syncthreads();
    }
    int excl = sh[threadIdx.x] - v + g_blocksum[blockIdx.x];
    if (i < N) { g_rowstart[i] = excl; g_cursor[i] = excl; }
    if (i == 0) g_rowstart[N] = E;
}

__global__ void k_reorder(const int* __restrict__ src, const int* __restrict__ dst, int E) {
    int e = blockIdx.x * blockDim.x + threadIdx.x;
    if (e < E) {
        int d = dst[e];
        int pos = atomicAdd(&g_cursor[d], 1);
        g_srcsorted[pos] = src[e];
    }
}

// ---------------- GEMM1: h1s = (x @ W1) * dinv ------------------------------
__global__ __launch_bounds__(256) void k_gemm1(const float* __restrict__ x,
                                               const float* __restrict__ W1, int N) {
    __shared__ float Ws[FIN * HID];
    __shared__ float xs[32][FIN + 1];

    const int tx = threadIdx.x;
    const int ty = threadIdx.y;
    const int t  = ty * 32 + tx;
    const int node0 = blockIdx.x * 32;

    #pragma unroll
    for (int i = t; i < FIN * HID; i += 256) Ws[i] = W1[i];
    for (int i = t; i < 32 * FIN; i += 256) {
        int r = i >> 7, c = i & 127;
        int node = node0 + r;
        xs[r][c] = (node < N) ? x[(size_t)node * FIN + c] : 0.f;
    }
    __syncthreads();

    float acc[8];
    #pragma unroll
    for (int j = 0; j < 8; j++) acc[j] = 0.f;
    const int jb = ty * 8;

    #pragma unroll 8
    for (int k = 0; k < FIN; k++) {
        float xv = xs[tx][k];
        #pragma unroll
        for (int j = 0; j < 8; j++) acc[j] += xv * Ws[k * HID + jb + j];
    }

    int node = node0 + tx;
    if (node < N) {
        float d = g_dinv[node];
        float* o = g_h1s + (size_t)node * HID + jb;
        #pragma unroll
        for (int j = 0; j < 8; j++) o[j] = acc[j] * d;
    }
}

// ---------------- agg1: out1 = relu(dinv*(gather-sum + self) + b1) ----------
// one warp per node, lane holds float2 (64 feats = 32 float2)
__global__ __launch_bounds__(256) void k_agg1(const float* __restrict__ b1, int N) {
    int w = (blockIdx.x * 256 + threadIdx.x) >> 5;
    int lane = threadIdx.x & 31;
    if (w >= N) return;
    int rs = g_rowstart[w], re = g_rowstart[w + 1];

    float2 acc = ((const float2*)(g_h1s + (size_t)w * HID))[lane];  // self term

    for (int base = rs; base < re; base += 32) {
        int n = re - base;
        int idx = (lane < n) ? g_srcsorted[base + lane] : 0;
        int cnt = n < 32 ? n : 32;
        for (int j = 0; j < cnt; j++) {
            int s = __shfl_sync(0xffffffffu, idx, j);
            float2 v = ((const float2*)(g_h1s + (size_t)s * HID))[lane];
            acc.x += v.x;
            acc.y += v.y;
        }
    }

    float d = g_dinv[w];
    float2 bb = ((const float2*)b1)[lane];
    float2 o;
    o.x = fmaxf(fmaf(d, acc.x, bb.x), 0.f);
    o.y = fmaxf(fmaf(d, acc.y, bb.y), 0.f);
    ((float2*)(g_out1 + (size_t)w * HID))[lane] = o;
}

// ---------------- GEMM2: h2s = (out1 @ W2) * dinv ---------------------------
__global__ __launch_bounds__(128) void k_gemm2(const float* __restrict__ W2, int N) {
    __shared__ float Ws[HID * CLS];
    __shared__ float xs[32][HID + 1];

    const int tx = threadIdx.x;
    const int ty = threadIdx.y;
    const int t  = ty * 32 + tx;
    const int node0 = blockIdx.x * 32;

    for (int i = t; i < HID * CLS; i += 128) Ws[i] = W2[i];
    for (int i = t; i < 32 * HID; i += 128) {
        int r = i >> 6, c = i & 63;
        int node = node0 + r;
        xs[r][c] = (node < N) ? g_out1[(size_t)node * HID + c] : 0.f;
    }
    __syncthreads();

    float acc[4] = {0.f, 0.f, 0.f, 0.f};
    const int jb = ty * 4;

    #pragma unroll 8
    for (int k = 0; k < HID; k++) {
        float xv = xs[tx][k];
        #pragma unroll
        for (int j = 0; j < 4; j++) acc[j] += xv * Ws[k * CLS + jb + j];
    }

    int node = node0 + tx;
    if (node < N) {
        float d = g_dinv[node];
        float* o = g_h2s + (size_t)node * CLS + jb;
        #pragma unroll
        for (int j = 0; j < 4; j++) o[j] = acc[j] * d;
    }
}

// ---------------- agg2 + combine + log_softmax (writes final output) --------
// 16 threads per node, lane c = class c
__global__ __launch_bounds__(256) void k_agg2(const float* __restrict__ b2,
                                              float* __restrict__ out, int N) {
    int g = (blockIdx.x * 256 + threadIdx.x) >> 4;
    int lane = threadIdx.x & 15;
    int seg = (threadIdx.x >> 4) & 1;                 // which half-warp
    unsigned mask = 0xFFFFu << (seg * 16);
    if (g >= N) return;

    int rs = g_rowstart[g], re = g_rowstart[g + 1];
    float acc = g_h2s[(size_t)g * CLS + lane];        // self term

    for (int base = rs; base < re; base += 16) {
        int n = re - base;
        int idx = (lane < n) ? g_srcsorted[base + lane] : 0;
        int cnt = n < 16 ? n : 16;
        for (int j = 0; j < cnt; j++) {
            int s = __shfl_sync(mask, idx, j, 16);
            acc += g_h2s[(size_t)s * CLS + lane];
        }
    }

    float d = g_dinv[g];
    float z = fmaxf(fmaf(d, acc, b2[lane]), 0.f);

    float m = z;
    #pragma unroll
    for (int off = 8; off; off >>= 1) m = fmaxf(m, __shfl_xor_sync(mask, m, off, 16));
    float e = expf(z - m);
    float ssum = e;
    #pragma unroll
    for (int off = 8; off; off >>= 1) ssum += __shfl_xor_sync(mask, ssum, off, 16);

    out[(size_t)g * CLS + lane] = z - (m + logf(ssum));
}

// ---------------- launcher ---------------------------------------------------
extern "C" void kernel_launch(void* const* d_in, const int* in_sizes, int n_in,
                              void* d_out, int out_size) {
    const float* x  = (const float*)d_in[0];
    const int*   ei = (const int*)d_in[1];
    const float* W1 = (const float*)d_in[2];
    const float* b1 = (const float*)d_in[3];
    const float* W2 = (const float*)d_in[4];
    const float* b2 = (const float*)d_in[5];
    float* out = (float*)d_out;

    const int N = in_sizes[0] / FIN;       // 100000
    const int E = in_sizes[1] / 2;         // 1600000
    const int* src = ei;
    const int* dst = ei + E;
    const int nb = (N + 1023) / 1024;

    k_zero_deg<<<(N + 255) / 256, 256>>>(N);
    k_deg<<<(E + 255) / 256, 256>>>(dst, E);
    k_dinv<<<(N + 255) / 256, 256>>>(N);

    k_scanA<<<nb, 1024>>>(N);
    k_scanB<<<1, 32>>>(nb);
    k_scanC<<<nb, 1024>>>(N, E);
    k_reorder<<<(E + 255) / 256, 256>>>(src, dst, E);

    dim3 b1d(32, 8);
    k_gemm1<<<(N + 31) / 32, b1d>>>(x, W1, N);

    {
        long long units = (long long)N * 32;
        k_agg1<<<(unsigned)((units + 255) / 256), 256>>>(b1, N);
    }

    dim3 b2d(32, 4);
    k_gemm2<<<(N + 31) / 32, b2d>>>(W2, N);

    {
        long long units = (long long)N * 16;
        k_agg2<<<(unsigned)((units + 255) / 256), 256>>>(b2, out, N);
    }
}

// round 3
// speedup vs baseline: 1.4218x; 1.3015x over previous
#include <cuda_runtime.h>
#include <math.h>

#define NN   100000
#define EE   1600000
#define FIN  128
#define HID  64
#define CLS  16

// ---------------- scratch (static __device__ allocations) -------------------
__device__ int   g_deg[NN];
__device__ int   g_rowstart[NN + 1];
__device__ int   g_cursor[NN];
__device__ int   g_srcsorted[EE];
__device__ int   g_blocksum[256];
__device__ float g_dinv[NN];
__device__ float g_h1s[(size_t)NN * HID];   // (x@W1) * dinv
__device__ float g_out1[(size_t)NN * HID];  // relu layer-1 output
__device__ float g_h2s[(size_t)NN * CLS];   // (out1@W2) * dinv

// ---------------- degree ----------------------------------------------------
__global__ void k_zero_deg(int n) {
    int i = blockIdx.x * blockDim.x + threadIdx.x;
    if (i < n) g_deg[i] = 0;
}

__global__ void k_deg(const int* __restrict__ dst, int E) {
    int e = blockIdx.x * blockDim.x + threadIdx.x;
    if (e < E) atomicAdd(&g_deg[dst[e]], 1);
}

// ---------------- CSR build: scan of degrees --------------------------------
__global__ __launch_bounds__(1024) void k_scanA(int N) {
    __shared__ int sh[1024];
    int i = blockIdx.x * 1024 + threadIdx.x;
    sh[threadIdx.x] = (i < N) ? g_deg[i] : 0;
    __syncthreads();
    #pragma unroll
    for (int off = 512; off; off >>= 1) {
        if (threadIdx.x < off) sh[threadIdx.x] += sh[threadIdx.x + off];
        __syncthreads();
    }
    if (threadIdx.x == 0) g_blocksum[blockIdx.x] = sh[0];
}

// parallel exclusive scan of the (<=128) block sums
__global__ __launch_bounds__(128) void k_scanB(int nb) {
    __shared__ int sh[128];
    int t = threadIdx.x;
    int v = (t < nb) ? g_blocksum[t] : 0;
    sh[t] = v;
    __syncthreads();
    #pragma unroll
    for (int off = 1; off < 128; off <<= 1) {
        int x = (t >= off) ? sh[t - off] : 0;
        __syncthreads();
        sh[t] += x;
        __syncthreads();
    }
    if (t < nb) g_blocksum[t] = sh[t] - v;   // exclusive
}

// scan within block + rowstart/cursor init + dinv (fused)
__global__ __launch_bounds__(1024) void k_scanC(int N, int E) {
    __shared__ int sh[1024];
    int i = blockIdx.x * 1024 + threadIdx.x;
    int v = (i < N) ? g_deg[i] : 0;
    sh[threadIdx.x] = v;
    __syncthreads();
    #pragma unroll
    for (int off = 1; off < 1024; off <<= 1) {
        int x = (threadIdx.x >= off) ? sh[threadIdx.x - off] : 0;
        __syncthreads();
        sh[threadIdx.x] += x;
        __syncthreads();
    }
    int excl = sh[threadIdx.x] - v + g_blocksum[blockIdx.x];
    if (i < N) {
        g_rowstart[i] = excl;
        g_cursor[i] = excl;
        g_dinv[i] = rsqrtf((float)v + 1.0f);
    }
    if (i == 0) g_rowstart[N] = E;
}

__global__ void k_reorder(const int* __restrict__ src, const int* __restrict__ dst, int E) {
    int e = blockIdx.x * blockDim.x + threadIdx.x;
    if (e < E) {
        int d = dst[e];
        int pos = atomicAdd(&g_cursor[d], 1);
        g_srcsorted[pos] = src[e];
    }
}

// ---------------- GEMM1 via 3xTF32 tensor cores -----------------------------
// h1s = (x @ W1) * dinv.  Tile: M=64 (4 warps x m16), N=64, K=128 resident.
__device__ __forceinline__ unsigned f2tf32(float f) {
    unsigned r;
    asm("cvt.rna.tf32.f32 %0, %1;" : "=r"(r) : "f"(f));
    return r;
}

#define PITCH 132
#define GEMM1_SMEM (3 * 64 * PITCH * 4)

__global__ __launch_bounds__(128) void k_gemm1(const float* __restrict__ x,
                                               const float* __restrict__ W1, int N) {
    extern __shared__ float smem[];
    float*    sA  = smem;                          // [64][PITCH] fp32
    unsigned* sBh = (unsigned*)(smem + 64 * PITCH);        // Wt hi [64][PITCH]
    unsigned* sBl = (unsigned*)(smem + 2 * 64 * PITCH);    // Wt lo

    const int tid  = threadIdx.x;
    const int node0 = blockIdx.x * 64;

    // fill A: 64 rows x 128 cols as float4
    for (int i = tid; i < 64 * 32; i += 128) {
        int r = i >> 5, c4 = i & 31;
        int node = node0 + r; if (node >= N) node = N - 1;
        float4 v = ((const float4*)(x + (size_t)node * FIN))[c4];
        float* p = sA + r * PITCH + c4 * 4;
        p[0] = v.x; p[1] = v.y; p[2] = v.z; p[3] = v.w;
    }
    // fill W transposed + split hi/lo: Wt[n][k]
    for (int i = tid; i < FIN * HID; i += 128) {
        int k = i >> 6, n = i & 63;
        float w = W1[i];
        unsigned hi = f2tf32(w);
        float lo_f = w - __uint_as_float(hi);
        sBh[n * PITCH + k] = hi;
        sBl[n * PITCH + k] = f2tf32(lo_f);
    }
    __syncthreads();

    const int warp = tid >> 5;
    const int lane = tid & 31;
    const int g = lane >> 2;      // 0..7
    const int r = lane & 3;       // 0..3
    const int row0 = warp * 16 + g;
    const int row1 = row0 + 8;

    float acc[8][4];
    #pragma unroll
    for (int t = 0; t < 8; t++)
        #pragma unroll
        for (int j = 0; j < 4; j++) acc[t][j] = 0.f;

    #pragma unroll
    for (int kt = 0; kt < 16; kt++) {
        const int k0 = kt * 8;
        float a0f = sA[row0 * PITCH + k0 + r];
        float a1f = sA[row1 * PITCH + k0 + r];
        float a2f = sA[row0 * PITCH + k0 + 4 + r];
        float a3f = sA[row1 * PITCH + k0 + 4 + r];
        unsigned ah0 = f2tf32(a0f), ah1 = f2tf32(a1f), ah2 = f2tf32(a2f), ah3 = f2tf32(a3f);
        unsigned al0 = f2tf32(a0f - __uint_as_float(ah0));
        unsigned al1 = f2tf32(a1f - __uint_as_float(ah1));
        unsigned al2 = f2tf32(a2f - __uint_as_float(ah2));
        unsigned al3 = f2tf32(a3f - __uint_as_float(ah3));

        #pragma unroll
        for (int t = 0; t < 8; t++) {
            const unsigned* bhp = sBh + (t * 8 + g) * PITCH + k0;
            const unsigned* blp = sBl + (t * 8 + g) * PITCH + k0;
            unsigned bh0 = bhp[r], bh1 = bhp[4 + r];
            unsigned bl0 = blp[r], bl1 = blp[4 + r];
            asm("mma.sync.aligned.m16n8k8.row.col.f32.tf32.tf32.f32 "
                "{%0,%1,%2,%3},{%4,%5,%6,%7},{%8,%9},{%0,%1,%2,%3};"
                : "+f"(acc[t][0]), "+f"(acc[t][1]), "+f"(acc[t][2]), "+f"(acc[t][3])
                : "r"(ah0), "r"(ah1), "r"(ah2), "r"(ah3), "r"(bh0), "r"(bh1));
            asm("mma.sync.aligned.m16n8k8.row.col.f32.tf32.tf32.f32 "
                "{%0,%1,%2,%3},{%4,%5,%6,%7},{%8,%9},{%0,%1,%2,%3};"
                : "+f"(acc[t][0]), "+f"(acc[t][1]), "+f"(acc[t][2]), "+f"(acc[t][3])
                : "r"(al0), "r"(al1), "r"(al2), "r"(al3), "r"(bh0), "r"(bh1));
            asm("mma.sync.aligned.m16n8k8.row.col.f32.tf32.tf32.f32 "
                "{%0,%1,%2,%3},{%4,%5,%6,%7},{%8,%9},{%0,%1,%2,%3};"
                : "+f"(acc[t][0]), "+f"(acc[t][1]), "+f"(acc[t][2]), "+f"(acc[t][3])
                : "r"(ah0), "r"(ah1), "r"(ah2), "r"(ah3), "r"(bl0), "r"(bl1));
        }
    }

    int n0 = node0 + row0;
    int n1 = node0 + row1;
    float d0 = (n0 < N) ? g_dinv[n0] : 0.f;
    float d1 = (n1 < N) ? g_dinv[n1] : 0.f;
    #pragma unroll
    for (int t = 0; t < 8; t++) {
        int col = t * 8 + 2 * r;
        if (n0 < N) {
            float2 v = make_float2(acc[t][0] * d0, acc[t][1] * d0);
            *(float2*)(g_h1s + (size_t)n0 * HID + col) = v;
        }
        if (n1 < N) {
            float2 v = make_float2(acc[t][2] * d1, acc[t][3] * d1);
            *(float2*)(g_h1s + (size_t)n1 * HID + col) = v;
        }
    }
}

// ---------------- agg1: out1 = relu(dinv*(gather-sum + self) + b1) ----------
__global__ __launch_bounds__(256) void k_agg1(const float* __restrict__ b1, int N) {
    int w = (blockIdx.x * 256 + threadIdx.x) >> 5;
    int lane = threadIdx.x & 31;
    if (w >= N) return;
    int rs = g_rowstart[w], re = g_rowstart[w + 1];

    float2 acc = ((const float2*)(g_h1s + (size_t)w * HID))[lane];  // self term

    for (int base = rs; base < re; base += 32) {
        int n = re - base;
        int idx = (lane < n) ? g_srcsorted[base + lane] : 0;
        int cnt = n < 32 ? n : 32;
        int j = 0;
        for (; j + 4 <= cnt; j += 4) {
            int s0 = __shfl_sync(0xffffffffu, idx, j);
            int s1 = __shfl_sync(0xffffffffu, idx, j + 1);
            int s2 = __shfl_sync(0xffffffffu, idx, j + 2);
            int s3 = __shfl_sync(0xffffffffu, idx, j + 3);
            float2 v0 = ((const float2*)(g_h1s + (size_t)s0 * HID))[lane];
            float2 v1 = ((const float2*)(g_h1s + (size_t)s1 * HID))[lane];
            float2 v2 = ((const float2*)(g_h1s + (size_t)s2 * HID))[lane];
            float2 v3 = ((const float2*)(g_h1s + (size_t)s3 * HID))[lane];
            acc.x += v0.x + v1.x + v2.x + v3.x;
            acc.y += v0.y + v1.y + v2.y + v3.y;
        }
        for (; j < cnt; j++) {
            int s = __shfl_sync(0xffffffffu, idx, j);
            float2 v = ((const float2*)(g_h1s + (size_t)s * HID))[lane];
            acc.x += v.x; acc.y += v.y;
        }
    }

    float d = g_dinv[w];
    float2 bb = ((const float2*)b1)[lane];
    float2 o;
    o.x = fmaxf(fmaf(d, acc.x, bb.x), 0.f);
    o.y = fmaxf(fmaf(d, acc.y, bb.y), 0.f);
    ((float2*)(g_out1 + (size_t)w * HID))[lane] = o;
}

// ---------------- GEMM2: h2s = (out1 @ W2) * dinv ---------------------------
__global__ __launch_bounds__(128) void k_gemm2(const float* __restrict__ W2, int N) {
    __shared__ float Ws[HID * CLS];
    __shared__ float xs[32][HID + 1];

    const int tx = threadIdx.x;
    const int ty = threadIdx.y;
    const int t  = ty * 32 + tx;
    const int node0 = blockIdx.x * 32;

    for (int i = t; i < HID * CLS; i += 128) Ws[i] = W2[i];
    for (int i = t; i < 32 * HID; i += 128) {
        int r = i >> 6, c = i & 63;
        int node = node0 + r;
        xs[r][c] = (node < N) ? g_out1[(size_t)node * HID + c] : 0.f;
    }
    __syncthreads();

    float acc[4] = {0.f, 0.f, 0.f, 0.f};
    const int jb = ty * 4;

    #pragma unroll 8
    for (int k = 0; k < HID; k++) {
        float xv = xs[tx][k];
        #pragma unroll
        for (int j = 0; j < 4; j++) acc[j] += xv * Ws[k * CLS + jb + j];
    }

    int node = node0 + tx;
    if (node < N) {
        float d = g_dinv[node];
        float* o = g_h2s + (size_t)node * CLS + jb;
        #pragma unroll
        for (int j = 0; j < 4; j++) o[j] = acc[j] * d;
    }
}

// ---------------- agg2 + combine + log_softmax ------------------------------
__global__ __launch_bounds__(256) void k_agg2(const float* __restrict__ b2,
                                              float* __restrict__ out, int N) {
    int g = (blockIdx.x * 256 + threadIdx.x) >> 4;
    int lane = threadIdx.x & 15;
    int seg = (threadIdx.x >> 4) & 1;
    unsigned mask = 0xFFFFu << (seg * 16);
    if (g >= N) return;

    int rs = g_rowstart[g], re = g_rowstart[g + 1];
    float acc = g_h2s[(size_t)g * CLS + lane];        // self term

    for (int base = rs; base < re; base += 16) {
        int n = re - base;
        int idx = (lane < n) ? g_srcsorted[base + lane] : 0;
        int cnt = n < 16 ? n : 16;
        int j = 0;
        for (; j + 4 <= cnt; j += 4) {
            int s0 = __shfl_sync(mask, idx, j, 16);
            int s1 = __shfl_sync(mask, idx, j + 1, 16);
            int s2 = __shfl_sync(mask, idx, j + 2, 16);
            int s3 = __shfl_sync(mask, idx, j + 3, 16);
            float v0 = g_h2s[(size_t)s0 * CLS + lane];
            float v1 = g_h2s[(size_t)s1 * CLS + lane];
            float v2 = g_h2s[(size_t)s2 * CLS + lane];
            float v3 = g_h2s[(size_t)s3 * CLS + lane];
            acc += v0 + v1 + v2 + v3;
        }
        for (; j < cnt; j++) {
            int s = __shfl_sync(mask, idx, j, 16);
            acc += g_h2s[(size_t)s * CLS + lane];
        }
    }

    float d = g_dinv[g];
    float z = fmaxf(fmaf(d, acc, b2[lane]), 0.f);

    float m = z;
    #pragma unroll
    for (int off = 8; off; off >>= 1) m = fmaxf(m, __shfl_xor_sync(mask, m, off, 16));
    float e = expf(z - m);
    float ssum = e;
    #pragma unroll
    for (int off = 8; off; off >>= 1) ssum += __shfl_xor_sync(mask, ssum, off, 16);

    out[(size_t)g * CLS + lane] = z - (m + logf(ssum));
}

// ---------------- launcher ---------------------------------------------------
extern "C" void kernel_launch(void* const* d_in, const int* in_sizes, int n_in,
                              void* d_out, int out_size) {
    const float* x  = (const float*)d_in[0];
    const int*   ei = (const int*)d_in[1];
    const float* W1 = (const float*)d_in[2];
    const float* b1 = (const float*)d_in[3];
    const float* W2 = (const float*)d_in[4];
    const float* b2 = (const float*)d_in[5];
    float* out = (float*)d_out;

    const int N = in_sizes[0] / FIN;       // 100000
    const int E = in_sizes[1] / 2;         // 1600000
    const int* src = ei;
    const int* dst = ei + E;
    const int nb = (N + 1023) / 1024;

    static int attr_done = 0;
    if (!attr_done) {
        cudaFuncSetAttribute(k_gemm1, cudaFuncAttributeMaxDynamicSharedMemorySize, GEMM1_SMEM);
        attr_done = 1;
    }

    k_zero_deg<<<(N + 255) / 256, 256>>>(N);
    k_deg<<<(E + 255) / 256, 256>>>(dst, E);

    k_scanA<<<nb, 1024>>>(N);
    k_scanB<<<1, 128>>>(nb);
    k_scanC<<<nb, 1024>>>(N, E);
    k_reorder<<<(E + 255) / 256, 256>>>(src, dst, E);

    k_gemm1<<<(N + 63) / 64, 128, GEMM1_SMEM>>>(x, W1, N);

    {
        long long units = (long long)N * 32;
        k_agg1<<<(unsigned)((units + 255) / 256), 256>>>(b1, N);
    }

    dim3 b2d(32, 4);
    k_gemm2<<<(N + 31) / 32, b2d>>>(W2, N);

    {
        long long units = (long long)N * 16;
        k_agg2<<<(unsigned)((units + 255) / 256), 256>>>(b2, out, N);
    }
}

// round 4
// speedup vs baseline: 1.5114x; 1.0631x over previous
#include <cuda_runtime.h>
#include <math.h>

#define NN   100000
#define EE   1600000
#define FIN  128
#define HID  64
#define CLS  16

// ---------------- scratch (static __device__ allocations) -------------------
__device__ int   g_deg[NN];
__device__ int   g_rowstart[NN + 1];
__device__ int   g_cursor[NN];
__device__ int   g_srcsorted[EE];
__device__ int   g_blocksum[256];
__device__ float g_dinv[NN];
__device__ float g_h1[(size_t)NN * HID];    // x@W1 (UNscaled)
__device__ float g_out1[(size_t)NN * HID];  // relu layer-1 output
__device__ float g_h2s[(size_t)NN * CLS];   // (out1@W2) * dinv

// ---------------- degree ----------------------------------------------------
__global__ void k_zero_deg(int n) {
    int i = blockIdx.x * blockDim.x + threadIdx.x;
    if (i < n) g_deg[i] = 0;
}

__global__ void k_deg(const int* __restrict__ dst, int E) {
    int e = blockIdx.x * blockDim.x + threadIdx.x;
    if (e < E) atomicAdd(&g_deg[dst[e]], 1);
}

// ---------------- CSR build: scan of degrees --------------------------------
__global__ __launch_bounds__(1024) void k_scanA(int N) {
    __shared__ int sh[1024];
    int i = blockIdx.x * 1024 + threadIdx.x;
    sh[threadIdx.x] = (i < N) ? g_deg[i] : 0;
    __syncthreads();
    #pragma unroll
    for (int off = 512; off; off >>= 1) {
        if (threadIdx.x < off) sh[threadIdx.x] += sh[threadIdx.x + off];
        __syncthreads();
    }
    if (threadIdx.x == 0) g_blocksum[blockIdx.x] = sh[0];
}

__global__ __launch_bounds__(128) void k_scanB(int nb) {
    __shared__ int sh[128];
    int t = threadIdx.x;
    int v = (t < nb) ? g_blocksum[t] : 0;
    sh[t] = v;
    __syncthreads();
    #pragma unroll
    for (int off = 1; off < 128; off <<= 1) {
        int x = (t >= off) ? sh[t - off] : 0;
        __syncthreads();
        sh[t] += x;
        __syncthreads();
    }
    if (t < nb) g_blocksum[t] = sh[t] - v;   // exclusive
}

__global__ __launch_bounds__(1024) void k_scanC(int N, int E) {
    __shared__ int sh[1024];
    int i = blockIdx.x * 1024 + threadIdx.x;
    int v = (i < N) ? g_deg[i] : 0;
    sh[threadIdx.x] = v;
    __syncthreads();
    #pragma unroll
    for (int off = 1; off < 1024; off <<= 1) {
        int x = (threadIdx.x >= off) ? sh[threadIdx.x - off] : 0;
        __syncthreads();
        sh[threadIdx.x] += x;
        __syncthreads();
    }
    int excl = sh[threadIdx.x] - v + g_blocksum[blockIdx.x];
    if (i < N) {
        g_rowstart[i] = excl;
        g_cursor[i] = excl;
        g_dinv[i] = rsqrtf((float)v + 1.0f);
    }
    if (i == 0) g_rowstart[N] = E;
}

__global__ void k_reorder(const int* __restrict__ src, const int* __restrict__ dst, int E) {
    int e = blockIdx.x * blockDim.x + threadIdx.x;
    if (e < E) {
        int d = dst[e];
        int pos = atomicAdd(&g_cursor[d], 1);
        g_srcsorted[pos] = src[e];
    }
}

// ---------------- GEMM1 via 3xTF32 tensor cores (h1 = x @ W1, unscaled) -----
__device__ __forceinline__ unsigned f2tf32(float f) {
    unsigned r;
    asm("cvt.rna.tf32.f32 %0, %1;" : "=r"(r) : "f"(f));
    return r;
}

#define PITCH 132
#define GEMM1_SMEM (3 * 64 * PITCH * 4)

__global__ __launch_bounds__(128) void k_gemm1(const float* __restrict__ x,
                                               const float* __restrict__ W1, int N) {
    extern __shared__ float smem[];
    float*    sA  = smem;
    unsigned* sBh = (unsigned*)(smem + 64 * PITCH);
    unsigned* sBl = (unsigned*)(smem + 2 * 64 * PITCH);

    const int tid  = threadIdx.x;
    const int node0 = blockIdx.x * 64;

    for (int i = tid; i < 64 * 32; i += 128) {
        int r = i >> 5, c4 = i & 31;
        int node = node0 + r; if (node >= N) node = N - 1;
        float4 v = ((const float4*)(x + (size_t)node * FIN))[c4];
        float* p = sA + r * PITCH + c4 * 4;
        p[0] = v.x; p[1] = v.y; p[2] = v.z; p[3] = v.w;
    }
    for (int i = tid; i < FIN * HID; i += 128) {
        int k = i >> 6, n = i & 63;
        float w = W1[i];
        unsigned hi = f2tf32(w);
        float lo_f = w - __uint_as_float(hi);
        sBh[n * PITCH + k] = hi;
        sBl[n * PITCH + k] = f2tf32(lo_f);
    }
    __syncthreads();

    const int warp = tid >> 5;
    const int lane = tid & 31;
    const int g = lane >> 2;
    const int r = lane & 3;
    const int row0 = warp * 16 + g;
    const int row1 = row0 + 8;

    float acc[8][4];
    #pragma unroll
    for (int t = 0; t < 8; t++)
        #pragma unroll
        for (int j = 0; j < 4; j++) acc[t][j] = 0.f;

    #pragma unroll
    for (int kt = 0; kt < 16; kt++) {
        const int k0 = kt * 8;
        float a0f = sA[row0 * PITCH + k0 + r];
        float a1f = sA[row1 * PITCH + k0 + r];
        float a2f = sA[row0 * PITCH + k0 + 4 + r];
        float a3f = sA[row1 * PITCH + k0 + 4 + r];
        unsigned ah0 = f2tf32(a0f), ah1 = f2tf32(a1f), ah2 = f2tf32(a2f), ah3 = f2tf32(a3f);
        unsigned al0 = f2tf32(a0f - __uint_as_float(ah0));
        unsigned al1 = f2tf32(a1f - __uint_as_float(ah1));
        unsigned al2 = f2tf32(a2f - __uint_as_float(ah2));
        unsigned al3 = f2tf32(a3f - __uint_as_float(ah3));

        #pragma unroll
        for (int t = 0; t < 8; t++) {
            const unsigned* bhp = sBh + (t * 8 + g) * PITCH + k0;
            const unsigned* blp = sBl + (t * 8 + g) * PITCH + k0;
            unsigned bh0 = bhp[r], bh1 = bhp[4 + r];
            unsigned bl0 = blp[r], bl1 = blp[4 + r];
            asm("mma.sync.aligned.m16n8k8.row.col.f32.tf32.tf32.f32 "
                "{%0,%1,%2,%3},{%4,%5,%6,%7},{%8,%9},{%0,%1,%2,%3};"
                : "+f"(acc[t][0]), "+f"(acc[t][1]), "+f"(acc[t][2]), "+f"(acc[t][3])
                : "r"(ah0), "r"(ah1), "r"(ah2), "r"(ah3), "r"(bh0), "r"(bh1));
            asm("mma.sync.aligned.m16n8k8.row.col.f32.tf32.tf32.f32 "
                "{%0,%1,%2,%3},{%4,%5,%6,%7},{%8,%9},{%0,%1,%2,%3};"
                : "+f"(acc[t][0]), "+f"(acc[t][1]), "+f"(acc[t][2]), "+f"(acc[t][3])
                : "r"(al0), "r"(al1), "r"(al2), "r"(al3), "r"(bh0), "r"(bh1));
            asm("mma.sync.aligned.m16n8k8.row.col.f32.tf32.tf32.f32 "
                "{%0,%1,%2,%3},{%4,%5,%6,%7},{%8,%9},{%0,%1,%2,%3};"
                : "+f"(acc[t][0]), "+f"(acc[t][1]), "+f"(acc[t][2]), "+f"(acc[t][3])
                : "r"(ah0), "r"(ah1), "r"(ah2), "r"(ah3), "r"(bl0), "r"(bl1));
        }
    }

    int n0 = node0 + row0;
    int n1 = node0 + row1;
    #pragma unroll
    for (int t = 0; t < 8; t++) {
        int col = t * 8 + 2 * r;
        if (n0 < N) {
            float2 v = make_float2(acc[t][0], acc[t][1]);
            *(float2*)(g_h1 + (size_t)n0 * HID + col) = v;
        }
        if (n1 < N) {
            float2 v = make_float2(acc[t][2], acc[t][3]);
            *(float2*)(g_h1 + (size_t)n1 * HID + col) = v;
        }
    }
}

// ---------------- agg1: out1 = relu(dinv_i*(Σ dinv_s*h1[s] + dinv_i*h1[i]) + b1)
__global__ __launch_bounds__(256) void k_agg1(const float* __restrict__ b1, int N) {
    int w = (blockIdx.x * 256 + threadIdx.x) >> 5;
    int lane = threadIdx.x & 31;
    if (w >= N) return;
    int rs = g_rowstart[w], re = g_rowstart[w + 1];
    float dw = g_dinv[w];

    float2 self = ((const float2*)(g_h1 + (size_t)w * HID))[lane];
    float2 acc = make_float2(dw * self.x, dw * self.y);

    for (int base = rs; base < re; base += 32) {
        int n = re - base;
        int idx = 0; float dv = 0.f;
        if (lane < n) { idx = g_srcsorted[base + lane]; dv = g_dinv[idx]; }
        int cnt = n < 32 ? n : 32;
        int j = 0;
        for (; j + 4 <= cnt; j += 4) {
            int s0 = __shfl_sync(0xffffffffu, idx, j);
            int s1 = __shfl_sync(0xffffffffu, idx, j + 1);
            int s2 = __shfl_sync(0xffffffffu, idx, j + 2);
            int s3 = __shfl_sync(0xffffffffu, idx, j + 3);
            float d0 = __shfl_sync(0xffffffffu, dv, j);
            float d1 = __shfl_sync(0xffffffffu, dv, j + 1);
            float d2 = __shfl_sync(0xffffffffu, dv, j + 2);
            float d3 = __shfl_sync(0xffffffffu, dv, j + 3);
            float2 v0 = ((const float2*)(g_h1 + (size_t)s0 * HID))[lane];
            float2 v1 = ((const float2*)(g_h1 + (size_t)s1 * HID))[lane];
            float2 v2 = ((const float2*)(g_h1 + (size_t)s2 * HID))[lane];
            float2 v3 = ((const float2*)(g_h1 + (size_t)s3 * HID))[lane];
            acc.x += d0 * v0.x + d1 * v1.x + d2 * v2.x + d3 * v3.x;
            acc.y += d0 * v0.y + d1 * v1.y + d2 * v2.y + d3 * v3.y;
        }
        for (; j < cnt; j++) {
            int s = __shfl_sync(0xffffffffu, idx, j);
            float d0 = __shfl_sync(0xffffffffu, dv, j);
            float2 v = ((const float2*)(g_h1 + (size_t)s * HID))[lane];
            acc.x += d0 * v.x; acc.y += d0 * v.y;
        }
    }

    float2 bb = ((const float2*)b1)[lane];
    float2 o;
    o.x = fmaxf(fmaf(dw, acc.x, bb.x), 0.f);
    o.y = fmaxf(fmaf(dw, acc.y, bb.y), 0.f);
    ((float2*)(g_out1 + (size_t)w * HID))[lane] = o;
}

// ---------------- GEMM2: h2s = (out1 @ W2) * dinv ---------------------------
__global__ __launch_bounds__(128) void k_gemm2(const float* __restrict__ W2, int N) {
    __shared__ float Ws[HID * CLS];
    __shared__ float xs[32][HID + 1];

    const int tx = threadIdx.x;
    const int ty = threadIdx.y;
    const int t  = ty * 32 + tx;
    const int node0 = blockIdx.x * 32;

    for (int i = t; i < HID * CLS; i += 128) Ws[i] = W2[i];
    for (int i = t; i < 32 * HID; i += 128) {
        int r = i >> 6, c = i & 63;
        int node = node0 + r;
        xs[r][c] = (node < N) ? g_out1[(size_t)node * HID + c] : 0.f;
    }
    __syncthreads();

    float acc[4] = {0.f, 0.f, 0.f, 0.f};
    const int jb = ty * 4;

    #pragma unroll 8
    for (int k = 0; k < HID; k++) {
        float xv = xs[tx][k];
        #pragma unroll
        for (int j = 0; j < 4; j++) acc[j] += xv * Ws[k * CLS + jb + j];
    }

    int node = node0 + tx;
    if (node < N) {
        float d = g_dinv[node];
        float* o = g_h2s + (size_t)node * CLS + jb;
        #pragma unroll
        for (int j = 0; j < 4; j++) o[j] = acc[j] * d;
    }
}

// ---------------- agg2 + combine + log_softmax ------------------------------
__global__ __launch_bounds__(256) void k_agg2(const float* __restrict__ b2,
                                              float* __restrict__ out, int N) {
    int g = (blockIdx.x * 256 + threadIdx.x) >> 4;
    int lane = threadIdx.x & 15;
    int seg = (threadIdx.x >> 4) & 1;
    unsigned mask = 0xFFFFu << (seg * 16);
    if (g >= N) return;

    int rs = g_rowstart[g], re = g_rowstart[g + 1];
    float acc = g_h2s[(size_t)g * CLS + lane];        // self term

    for (int base = rs; base < re; base += 16) {
        int n = re - base;
        int idx = (lane < n) ? g_srcsorted[base + lane] : 0;
        int cnt = n < 16 ? n : 16;
        int j = 0;
        for (; j + 4 <= cnt; j += 4) {
            int s0 = __shfl_sync(mask, idx, j, 16);
            int s1 = __shfl_sync(mask, idx, j + 1, 16);
            int s2 = __shfl_sync(mask, idx, j + 2, 16);
            int s3 = __shfl_sync(mask, idx, j + 3, 16);
            float v0 = g_h2s[(size_t)s0 * CLS + lane];
            float v1 = g_h2s[(size_t)s1 * CLS + lane];
            float v2 = g_h2s[(size_t)s2 * CLS + lane];
            float v3 = g_h2s[(size_t)s3 * CLS + lane];
            acc += v0 + v1 + v2 + v3;
        }
        for (; j < cnt; j++) {
            int s = __shfl_sync(mask, idx, j, 16);
            acc += g_h2s[(size_t)s * CLS + lane];
        }
    }

    float d = g_dinv[g];
    float z = fmaxf(fmaf(d, acc, b2[lane]), 0.f);

    float m = z;
    #pragma unroll
    for (int off = 8; off; off >>= 1) m = fmaxf(m, __shfl_xor_sync(mask, m, off, 16));
    float e = expf(z - m);
    float ssum = e;
    #pragma unroll
    for (int off = 8; off; off >>= 1) ssum += __shfl_xor_sync(mask, ssum, off, 16);

    out[(size_t)g * CLS + lane] = z - (m + logf(ssum));
}

// ---------------- launcher ---------------------------------------------------
extern "C" void kernel_launch(void* const* d_in, const int* in_sizes, int n_in,
                              void* d_out, int out_size) {
    const float* x  = (const float*)d_in[0];
    const int*   ei = (const int*)d_in[1];
    const float* W1 = (const float*)d_in[2];
    const float* b1 = (const float*)d_in[3];
    const float* W2 = (const float*)d_in[4];
    const float* b2 = (const float*)d_in[5];
    float* out = (float*)d_out;

    const int N = in_sizes[0] / FIN;       // 100000
    const int E = in_sizes[1] / 2;         // 1600000
    const int* src = ei;
    const int* dst = ei + E;
    const int nb = (N + 1023) / 1024;

    static cudaStream_t s2 = nullptr;
    static cudaEvent_t evFork = nullptr, evJoin = nullptr;
    static int init_done = 0;
    if (!init_done) {
        cudaFuncSetAttribute(k_gemm1, cudaFuncAttributeMaxDynamicSharedMemorySize, GEMM1_SMEM);
        cudaStreamCreateWithFlags(&s2, cudaStreamNonBlocking);
        cudaEventCreateWithFlags(&evFork, cudaEventDisableTiming);
        cudaEventCreateWithFlags(&evJoin, cudaEventDisableTiming);
        init_done = 1;
    }

    // Fork: gemm1 (x,W1 only) runs concurrently with the CSR build chain.
    cudaEventRecord(evFork, 0);
    cudaStreamWaitEvent(s2, evFork, 0);
    k_gemm1<<<(N + 63) / 64, 128, GEMM1_SMEM, s2>>>(x, W1, N);
    cudaEventRecord(evJoin, s2);

    // CSR build chain on the main (capture) stream.
    k_zero_deg<<<(N + 255) / 256, 256>>>(N);
    k_deg<<<(E + 255) / 256, 256>>>(dst, E);
    k_scanA<<<nb, 1024>>>(N);
    k_scanB<<<1, 128>>>(nb);
    k_scanC<<<nb, 1024>>>(N, E);
    k_reorder<<<(E + 255) / 256, 256>>>(src, dst, E);

    // Join: agg1 needs both h1 and the CSR.
    cudaStreamWaitEvent(0, evJoin, 0);

    {
        long long units = (long long)N * 32;
        k_agg1<<<(unsigned)((units + 255) / 256), 256>>>(b1, N);
    }

    dim3 b2d(32, 4);
    k_gemm2<<<(N + 31) / 32, b2d>>>(W2, N);

    {
        long long units = (long long)N * 16;
        k_agg2<<<(unsigned)((units + 255) / 256), 256>>>(b2, out, N);
    }
}

// round 5
// speedup vs baseline: 1.5538x; 1.0280x over previous
#include <cuda_runtime.h>
#include <cuda_fp16.h>
#include <math.h>

#define NN   100000
#define EE   1600000
#define FIN  128
#define HID  64
#define CLS  16

// ---------------- scratch (static __device__ allocations) -------------------
__device__ int    g_deg[NN];
__device__ int    g_rowstart[NN + 1];
__device__ int    g_cursor[NN];
__device__ int    g_srcsorted[EE];
__device__ int    g_blocksum[256];
__device__ float  g_dinv[NN];
__device__ __half g_h1h[(size_t)NN * HID];   // x@W1 (UNscaled) as fp16 messages
__device__ float  g_out1[(size_t)NN * HID];  // relu layer-1 output (fp32)
__device__ __half g_h2sh[(size_t)NN * CLS];  // (out1@W2)*dinv as fp16 messages

// ---------------- degree ----------------------------------------------------
__global__ void k_zero_deg(int n) {
    int i = blockIdx.x * blockDim.x + threadIdx.x;
    if (i < n) g_deg[i] = 0;
}

__global__ void k_deg(const int* __restrict__ dst, int E) {
    int e = blockIdx.x * blockDim.x + threadIdx.x;
    if (e < E) atomicAdd(&g_deg[dst[e]], 1);
}

// ---------------- CSR build: scan of degrees --------------------------------
__global__ __launch_bounds__(1024) void k_scanA(int N) {
    __shared__ int sh[1024];
    int i = blockIdx.x * 1024 + threadIdx.x;
    sh[threadIdx.x] = (i < N) ? g_deg[i] : 0;
    __syncthreads();
    #pragma unroll
    for (int off = 512; off; off >>= 1) {
        if (threadIdx.x < off) sh[threadIdx.x] += sh[threadIdx.x + off];
        __syncthreads();
    }
    if (threadIdx.x == 0) g_blocksum[blockIdx.x] = sh[0];
}

__global__ __launch_bounds__(128) void k_scanB(int nb) {
    __shared__ int sh[128];
    int t = threadIdx.x;
    int v = (t < nb) ? g_blocksum[t] : 0;
    sh[t] = v;
    __syncthreads();
    #pragma unroll
    for (int off = 1; off < 128; off <<= 1) {
        int x = (t >= off) ? sh[t - off] : 0;
        __syncthreads();
        sh[t] += x;
        __syncthreads();
    }
    if (t < nb) g_blocksum[t] = sh[t] - v;   // exclusive
}

__global__ __launch_bounds__(1024) void k_scanC(int N, int E) {
    __shared__ int sh[1024];
    int i = blockIdx.x * 1024 + threadIdx.x;
    int v = (i < N) ? g_deg[i] : 0;
    sh[threadIdx.x] = v;
    __syncthreads();
    #pragma unroll
    for (int off = 1; off < 1024; off <<= 1) {
        int x = (threadIdx.x >= off) ? sh[threadIdx.x - off] : 0;
        __syncthreads();
        sh[threadIdx.x] += x;
        __syncthreads();
    }
    int excl = sh[threadIdx.x] - v + g_blocksum[blockIdx.x];
    if (i < N) {
        g_rowstart[i] = excl;
        g_cursor[i] = excl;
        g_dinv[i] = rsqrtf((float)v + 1.0f);
    }
    if (i == 0) g_rowstart[N] = E;
}

__global__ void k_reorder(const int* __restrict__ src, const int* __restrict__ dst, int E) {
    int e = blockIdx.x * blockDim.x + threadIdx.x;
    if (e < E) {
        int d = dst[e];
        int pos = atomicAdd(&g_cursor[d], 1);
        g_srcsorted[pos] = src[e];
    }
}

// ---------------- GEMM1 via 3xTF32 tensor cores (h1 = x @ W1, fp16 out) -----
__device__ __forceinline__ unsigned f2tf32(float f) {
    unsigned r;
    asm("cvt.rna.tf32.f32 %0, %1;" : "=r"(r) : "f"(f));
    return r;
}

#define PITCH 132
#define GEMM1_SMEM (3 * 64 * PITCH * 4)

__global__ __launch_bounds__(128) void k_gemm1(const float* __restrict__ x,
                                               const float* __restrict__ W1, int N) {
    extern __shared__ float smem[];
    float*    sA  = smem;
    unsigned* sBh = (unsigned*)(smem + 64 * PITCH);
    unsigned* sBl = (unsigned*)(smem + 2 * 64 * PITCH);

    const int tid  = threadIdx.x;
    const int node0 = blockIdx.x * 64;

    for (int i = tid; i < 64 * 32; i += 128) {
        int r = i >> 5, c4 = i & 31;
        int node = node0 + r; if (node >= N) node = N - 1;
        float4 v = ((const float4*)(x + (size_t)node * FIN))[c4];
        float* p = sA + r * PITCH + c4 * 4;
        p[0] = v.x; p[1] = v.y; p[2] = v.z; p[3] = v.w;
    }
    for (int i = tid; i < FIN * HID; i += 128) {
        int k = i >> 6, n = i & 63;
        float w = W1[i];
        unsigned hi = f2tf32(w);
        float lo_f = w - __uint_as_float(hi);
        sBh[n * PITCH + k] = hi;
        sBl[n * PITCH + k] = f2tf32(lo_f);
    }
    __syncthreads();

    const int warp = tid >> 5;
    const int lane = tid & 31;
    const int g = lane >> 2;
    const int r = lane & 3;
    const int row0 = warp * 16 + g;
    const int row1 = row0 + 8;

    float acc[8][4];
    #pragma unroll
    for (int t = 0; t < 8; t++)
        #pragma unroll
        for (int j = 0; j < 4; j++) acc[t][j] = 0.f;

    #pragma unroll
    for (int kt = 0; kt < 16; kt++) {
        const int k0 = kt * 8;
        float a0f = sA[row0 * PITCH + k0 + r];
        float a1f = sA[row1 * PITCH + k0 + r];
        float a2f = sA[row0 * PITCH + k0 + 4 + r];
        float a3f = sA[row1 * PITCH + k0 + 4 + r];
        unsigned ah0 = f2tf32(a0f), ah1 = f2tf32(a1f), ah2 = f2tf32(a2f), ah3 = f2tf32(a3f);
        unsigned al0 = f2tf32(a0f - __uint_as_float(ah0));
        unsigned al1 = f2tf32(a1f - __uint_as_float(ah1));
        unsigned al2 = f2tf32(a2f - __uint_as_float(ah2));
        unsigned al3 = f2tf32(a3f - __uint_as_float(ah3));

        #pragma unroll
        for (int t = 0; t < 8; t++) {
            const unsigned* bhp = sBh + (t * 8 + g) * PITCH + k0;
            const unsigned* blp = sBl + (t * 8 + g) * PITCH + k0;
            unsigned bh0 = bhp[r], bh1 = bhp[4 + r];
            unsigned bl0 = blp[r], bl1 = blp[4 + r];
            asm("mma.sync.aligned.m16n8k8.row.col.f32.tf32.tf32.f32 "
                "{%0,%1,%2,%3},{%4,%5,%6,%7},{%8,%9},{%0,%1,%2,%3};"
                : "+f"(acc[t][0]), "+f"(acc[t][1]), "+f"(acc[t][2]), "+f"(acc[t][3])
                : "r"(ah0), "r"(ah1), "r"(ah2), "r"(ah3), "r"(bh0), "r"(bh1));
            asm("mma.sync.aligned.m16n8k8.row.col.f32.tf32.tf32.f32 "
                "{%0,%1,%2,%3},{%4,%5,%6,%7},{%8,%9},{%0,%1,%2,%3};"
                : "+f"(acc[t][0]), "+f"(acc[t][1]), "+f"(acc[t][2]), "+f"(acc[t][3])
                : "r"(al0), "r"(al1), "r"(al2), "r"(al3), "r"(bh0), "r"(bh1));
            asm("mma.sync.aligned.m16n8k8.row.col.f32.tf32.tf32.f32 "
                "{%0,%1,%2,%3},{%4,%5,%6,%7},{%8,%9},{%0,%1,%2,%3};"
                : "+f"(acc[t][0]), "+f"(acc[t][1]), "+f"(acc[t][2]), "+f"(acc[t][3])
                : "r"(ah0), "r"(ah1), "r"(ah2), "r"(ah3), "r"(bl0), "r"(bl1));
        }
    }

    int n0 = node0 + row0;
    int n1 = node0 + row1;
    #pragma unroll
    for (int t = 0; t < 8; t++) {
        int col = t * 8 + 2 * r;
        if (n0 < N)
            *(__half2*)(g_h1h + (size_t)n0 * HID + col) = __floats2half2_rn(acc[t][0], acc[t][1]);
        if (n1 < N)
            *(__half2*)(g_h1h + (size_t)n1 * HID + col) = __floats2half2_rn(acc[t][2], acc[t][3]);
    }
}

// ---------------- agg1: out1 = relu(dinv_i*(Σ dinv_s*h1[s] + dinv_i*h1[i]) + b1)
__global__ __launch_bounds__(256) void k_agg1(const float* __restrict__ b1, int N) {
    int w = (blockIdx.x * 256 + threadIdx.x) >> 5;
    int lane = threadIdx.x & 31;
    if (w >= N) return;
    int rs = g_rowstart[w], re = g_rowstart[w + 1];
    float dw = g_dinv[w];

    float2 self = __half22float2(((const __half2*)(g_h1h + (size_t)w * HID))[lane]);
    float2 acc = make_float2(dw * self.x, dw * self.y);

    for (int base = rs; base < re; base += 32) {
        int n = re - base;
        int idx = 0; float dv = 0.f;
        if (lane < n) { idx = g_srcsorted[base + lane]; dv = g_dinv[idx]; }
        int cnt = n < 32 ? n : 32;
        int j = 0;
        for (; j + 4 <= cnt; j += 4) {
            int s0 = __shfl_sync(0xffffffffu, idx, j);
            int s1 = __shfl_sync(0xffffffffu, idx, j + 1);
            int s2 = __shfl_sync(0xffffffffu, idx, j + 2);
            int s3 = __shfl_sync(0xffffffffu, idx, j + 3);
            float d0 = __shfl_sync(0xffffffffu, dv, j);
            float d1 = __shfl_sync(0xffffffffu, dv, j + 1);
            float d2 = __shfl_sync(0xffffffffu, dv, j + 2);
            float d3 = __shfl_sync(0xffffffffu, dv, j + 3);
            float2 v0 = __half22float2(((const __half2*)(g_h1h + (size_t)s0 * HID))[lane]);
            float2 v1 = __half22float2(((const __half2*)(g_h1h + (size_t)s1 * HID))[lane]);
            float2 v2 = __half22float2(((const __half2*)(g_h1h + (size_t)s2 * HID))[lane]);
            float2 v3 = __half22float2(((const __half2*)(g_h1h + (size_t)s3 * HID))[lane]);
            acc.x += d0 * v0.x + d1 * v1.x + d2 * v2.x + d3 * v3.x;
            acc.y += d0 * v0.y + d1 * v1.y + d2 * v2.y + d3 * v3.y;
        }
        for (; j < cnt; j++) {
            int s = __shfl_sync(0xffffffffu, idx, j);
            float d0 = __shfl_sync(0xffffffffu, dv, j);
            float2 v = __half22float2(((const __half2*)(g_h1h + (size_t)s * HID))[lane]);
            acc.x += d0 * v.x; acc.y += d0 * v.y;
        }
    }

    float2 bb = ((const float2*)b1)[lane];
    float2 o;
    o.x = fmaxf(fmaf(dw, acc.x, bb.x), 0.f);
    o.y = fmaxf(fmaf(dw, acc.y, bb.y), 0.f);
    ((float2*)(g_out1 + (size_t)w * HID))[lane] = o;
}

// ---------------- GEMM2: h2s = (out1 @ W2) * dinv  (fp16 out) ---------------
__global__ __launch_bounds__(128) void k_gemm2(const float* __restrict__ W2, int N) {
    __shared__ float Ws[HID * CLS];
    __shared__ float xs[32][HID + 1];

    const int tx = threadIdx.x;
    const int ty = threadIdx.y;
    const int t  = ty * 32 + tx;
    const int node0 = blockIdx.x * 32;

    for (int i = t; i < HID * CLS; i += 128) Ws[i] = W2[i];
    for (int i = t; i < 32 * HID; i += 128) {
        int r = i >> 6, c = i & 63;
        int node = node0 + r;
        xs[r][c] = (node < N) ? g_out1[(size_t)node * HID + c] : 0.f;
    }
    __syncthreads();

    float acc[4] = {0.f, 0.f, 0.f, 0.f};
    const int jb = ty * 4;

    #pragma unroll 8
    for (int k = 0; k < HID; k++) {
        float xv = xs[tx][k];
        #pragma unroll
        for (int j = 0; j < 4; j++) acc[j] += xv * Ws[k * CLS + jb + j];
    }

    int node = node0 + tx;
    if (node < N) {
        float d = g_dinv[node];
        __half2* o = (__half2*)(g_h2sh + (size_t)node * CLS + jb);
        o[0] = __floats2half2_rn(acc[0] * d, acc[1] * d);
        o[1] = __floats2half2_rn(acc[2] * d, acc[3] * d);
    }
}

// ---------------- agg2 + combine + log_softmax ------------------------------
__global__ __launch_bounds__(256) void k_agg2(const float* __restrict__ b2,
                                              float* __restrict__ out, int N) {
    int g = (blockIdx.x * 256 + threadIdx.x) >> 4;
    int lane = threadIdx.x & 15;
    int seg = (threadIdx.x >> 4) & 1;
    unsigned mask = 0xFFFFu << (seg * 16);
    if (g >= N) return;

    int rs = g_rowstart[g], re = g_rowstart[g + 1];
    float acc = __half2float(g_h2sh[(size_t)g * CLS + lane]);   // self term

    for (int base = rs; base < re; base += 16) {
        int n = re - base;
        int idx = (lane < n) ? g_srcsorted[base + lane] : 0;
        int cnt = n < 16 ? n : 16;
        int j = 0;
        for (; j + 4 <= cnt; j += 4) {
            int s0 = __shfl_sync(mask, idx, j, 16);
            int s1 = __shfl_sync(mask, idx, j + 1, 16);
            int s2 = __shfl_sync(mask, idx, j + 2, 16);
            int s3 = __shfl_sync(mask, idx, j + 3, 16);
            float v0 = __half2float(g_h2sh[(size_t)s0 * CLS + lane]);
            float v1 = __half2float(g_h2sh[(size_t)s1 * CLS + lane]);
            float v2 = __half2float(g_h2sh[(size_t)s2 * CLS + lane]);
            float v3 = __half2float(g_h2sh[(size_t)s3 * CLS + lane]);
            acc += v0 + v1 + v2 + v3;
        }
        for (; j < cnt; j++) {
            int s = __shfl_sync(mask, idx, j, 16);
            acc += __half2float(g_h2sh[(size_t)s * CLS + lane]);
        }
    }

    float d = g_dinv[g];
    float z = fmaxf(fmaf(d, acc, b2[lane]), 0.f);

    float m = z;
    #pragma unroll
    for (int off = 8; off; off >>= 1) m = fmaxf(m, __shfl_xor_sync(mask, m, off, 16));
    float e = expf(z - m);
    float ssum = e;
    #pragma unroll
    for (int off = 8; off; off >>= 1) ssum += __shfl_xor_sync(mask, ssum, off, 16);

    out[(size_t)g * CLS + lane] = z - (m + logf(ssum));
}

// ---------------- launcher ---------------------------------------------------
extern "C" void kernel_launch(void* const* d_in, const int* in_sizes, int n_in,
                              void* d_out, int out_size) {
    const float* x  = (const float*)d_in[0];
    const int*   ei = (const int*)d_in[1];
    const float* W1 = (const float*)d_in[2];
    const float* b1 = (const float*)d_in[3];
    const float* W2 = (const float*)d_in[4];
    const float* b2 = (const float*)d_in[5];
    float* out = (float*)d_out;

    const int N = in_sizes[0] / FIN;       // 100000
    const int E = in_sizes[1] / 2;         // 1600000
    const int* src = ei;
    const int* dst = ei + E;
    const int nb = (N + 1023) / 1024;

    static cudaStream_t s2 = nullptr;
    static cudaEvent_t evFork = nullptr, evJoin = nullptr;
    static int init_done = 0;
    if (!init_done) {
        cudaFuncSetAttribute(k_gemm1, cudaFuncAttributeMaxDynamicSharedMemorySize, GEMM1_SMEM);
        cudaStreamCreateWithFlags(&s2, cudaStreamNonBlocking);
        cudaEventCreateWithFlags(&evFork, cudaEventDisableTiming);
        cudaEventCreateWithFlags(&evJoin, cudaEventDisableTiming);
        init_done = 1;
    }

    // Fork: gemm1 (x,W1 only) runs concurrently with the CSR build chain.
    cudaEventRecord(evFork, 0);
    cudaStreamWaitEvent(s2, evFork, 0);
    k_gemm1<<<(N + 63) / 64, 128, GEMM1_SMEM, s2>>>(x, W1, N);
    cudaEventRecord(evJoin, s2);

    // CSR build chain on the main (capture) stream.
    k_zero_deg<<<(N + 255) / 256, 256>>>(N);
    k_deg<<<(E + 255) / 256, 256>>>(dst, E);
    k_scanA<<<nb, 1024>>>(N);
    k_scanB<<<1, 128>>>(nb);
    k_scanC<<<nb, 1024>>>(N, E);
    k_reorder<<<(E + 255) / 256, 256>>>(src, dst, E);

    // Join: agg1 needs both h1 and the CSR.
    cudaStreamWaitEvent(0, evJoin, 0);

    {
        long long units = (long long)N * 32;
        k_agg1<<<(unsigned)((units + 255) / 256), 256>>>(b1, N);
    }

    dim3 b2d(32, 4);
    k_gemm2<<<(N + 31) / 32, b2d>>>(W2, N);

    {
        long long units = (long long)N * 16;
        k_agg2<<<(unsigned)((units + 255) / 256), 256>>>(b2, out, N);
    }
}

// round 6
// speedup vs baseline: 1.6552x; 1.0652x over previous
#include <cuda_runtime.h>
#include <cuda_fp16.h>
#include <math.h>

#define NN   100000
#define EE   1600000
#define FIN  128
#define HID  64
#define CLS  16

// ---------------- scratch (static __device__ allocations) -------------------
__device__ int    g_deg[NN];
__device__ int    g_rowstart[NN + 1];
__device__ int    g_cursor[NN];
__device__ int2   g_edge[EE];                // (src, dinv[src] bits) sorted by dst
__device__ int    g_blocksum[256];
__device__ float  g_dinv[NN];
__device__ __half g_h1h[(size_t)NN * HID];   // x@W1 (UNscaled) fp16 messages
__device__ __half g_h2sh[(size_t)NN * CLS];  // (relu-out1@W2)*dinv fp16 messages

// ---------------- degree ----------------------------------------------------
__global__ void k_zero_deg(int n) {
    int i = blockIdx.x * blockDim.x + threadIdx.x;
    if (i < n) g_deg[i] = 0;
}

__global__ void k_deg(const int* __restrict__ dst, int E) {
    int e = blockIdx.x * blockDim.x + threadIdx.x;
    if (e < E) atomicAdd(&g_deg[dst[e]], 1);
}

// ---------------- CSR build -------------------------------------------------
__global__ __launch_bounds__(1024) void k_scanA(int N) {
    __shared__ int sh[1024];
    int i = blockIdx.x * 1024 + threadIdx.x;
    sh[threadIdx.x] = (i < N) ? g_deg[i] : 0;
    __syncthreads();
    #pragma unroll
    for (int off = 512; off; off >>= 1) {
        if (threadIdx.x < off) sh[threadIdx.x] += sh[threadIdx.x + off];
        __syncthreads();
    }
    if (threadIdx.x == 0) g_blocksum[blockIdx.x] = sh[0];
}

// scan within block + global prefix from redundant blocksum scan + dinv
__global__ __launch_bounds__(1024) void k_scanC(int N, int E, int nb) {
    __shared__ int sh[1024];
    __shared__ int bs[128];
    const int tid = threadIdx.x;
    int i = blockIdx.x * 1024 + tid;
    int v = (i < N) ? g_deg[i] : 0;
    sh[tid] = v;
    if (tid < 128) bs[tid] = (tid < nb) ? g_blocksum[tid] : 0;
    __syncthreads();
    // inclusive scan of bs (first 128 threads), all threads hit the barriers
    #pragma unroll
    for (int off = 1; off < 128; off <<= 1) {
        int x = 0;
        if (tid < 128 && tid >= off) x = bs[tid - off];
        __syncthreads();
        if (tid < 128) bs[tid] += x;
        __syncthreads();
    }
    // main block scan
    #pragma unroll
    for (int off = 1; off < 1024; off <<= 1) {
        int x = (tid >= off) ? sh[tid - off] : 0;
        __syncthreads();
        sh[tid] += x;
        __syncthreads();
    }
    int blockpref = (blockIdx.x == 0) ? 0 : bs[blockIdx.x - 1];
    int excl = sh[tid] - v + blockpref;
    if (i < N) {
        g_rowstart[i] = excl;
        g_cursor[i] = excl;
        g_dinv[i] = rsqrtf((float)v + 1.0f);
    }
    if (i == 0) g_rowstart[N] = E;
}

__global__ void k_reorder(const int* __restrict__ src, const int* __restrict__ dst, int E) {
    int e = blockIdx.x * blockDim.x + threadIdx.x;
    if (e < E) {
        int d = dst[e];
        int pos = atomicAdd(&g_cursor[d], 1);
        int s = src[e];
        g_edge[pos] = make_int2(s, __float_as_int(g_dinv[s]));
    }
}

// ---------------- GEMM1 via 3xTF32 tensor cores (h1 = x @ W1, fp16 out) -----
__device__ __forceinline__ unsigned f2tf32(float f) {
    unsigned r;
    asm("cvt.rna.tf32.f32 %0, %1;" : "=r"(r) : "f"(f));
    return r;
}

#define PITCH 132
#define GEMM1_SMEM (3 * 64 * PITCH * 4)

__global__ __launch_bounds__(128) void k_gemm1(const float* __restrict__ x,
                                               const float* __restrict__ W1, int N) {
    extern __shared__ float smem[];
    float*    sA  = smem;
    unsigned* sBh = (unsigned*)(smem + 64 * PITCH);
    unsigned* sBl = (unsigned*)(smem + 2 * 64 * PITCH);

    const int tid  = threadIdx.x;
    const int node0 = blockIdx.x * 64;

    for (int i = tid; i < 64 * 32; i += 128) {
        int r = i >> 5, c4 = i & 31;
        int node = node0 + r; if (node >= N) node = N - 1;
        float4 v = ((const float4*)(x + (size_t)node * FIN))[c4];
        float* p = sA + r * PITCH + c4 * 4;
        p[0] = v.x; p[1] = v.y; p[2] = v.z; p[3] = v.w;
    }
    for (int i = tid; i < FIN * HID; i += 128) {
        int k = i >> 6, n = i & 63;
        float w = W1[i];
        unsigned hi = f2tf32(w);
        float lo_f = w - __uint_as_float(hi);
        sBh[n * PITCH + k] = hi;
        sBl[n * PITCH + k] = f2tf32(lo_f);
    }
    __syncthreads();

    const int warp = tid >> 5;
    const int lane = tid & 31;
    const int g = lane >> 2;
    const int r = lane & 3;
    const int row0 = warp * 16 + g;
    const int row1 = row0 + 8;

    float acc[8][4];
    #pragma unroll
    for (int t = 0; t < 8; t++)
        #pragma unroll
        for (int j = 0; j < 4; j++) acc[t][j] = 0.f;

    #pragma unroll
    for (int kt = 0; kt < 16; kt++) {
        const int k0 = kt * 8;
        float a0f = sA[row0 * PITCH + k0 + r];
        float a1f = sA[row1 * PITCH + k0 + r];
        float a2f = sA[row0 * PITCH + k0 + 4 + r];
        float a3f = sA[row1 * PITCH + k0 + 4 + r];
        unsigned ah0 = f2tf32(a0f), ah1 = f2tf32(a1f), ah2 = f2tf32(a2f), ah3 = f2tf32(a3f);
        unsigned al0 = f2tf32(a0f - __uint_as_float(ah0));
        unsigned al1 = f2tf32(a1f - __uint_as_float(ah1));
        unsigned al2 = f2tf32(a2f - __uint_as_float(ah2));
        unsigned al3 = f2tf32(a3f - __uint_as_float(ah3));

        #pragma unroll
        for (int t = 0; t < 8; t++) {
            const unsigned* bhp = sBh + (t * 8 + g) * PITCH + k0;
            const unsigned* blp = sBl + (t * 8 + g) * PITCH + k0;
            unsigned bh0 = bhp[r], bh1 = bhp[4 + r];
            unsigned bl0 = blp[r], bl1 = blp[4 + r];
            asm("mma.sync.aligned.m16n8k8.row.col.f32.tf32.tf32.f32 "
                "{%0,%1,%2,%3},{%4,%5,%6,%7},{%8,%9},{%0,%1,%2,%3};"
                : "+f"(acc[t][0]), "+f"(acc[t][1]), "+f"(acc[t][2]), "+f"(acc[t][3])
                : "r"(ah0), "r"(ah1), "r"(ah2), "r"(ah3), "r"(bh0), "r"(bh1));
            asm("mma.sync.aligned.m16n8k8.row.col.f32.tf32.tf32.f32 "
                "{%0,%1,%2,%3},{%4,%5,%6,%7},{%8,%9},{%0,%1,%2,%3};"
                : "+f"(acc[t][0]), "+f"(acc[t][1]), "+f"(acc[t][2]), "+f"(acc[t][3])
                : "r"(al0), "r"(al1), "r"(al2), "r"(al3), "r"(bh0), "r"(bh1));
            asm("mma.sync.aligned.m16n8k8.row.col.f32.tf32.tf32.f32 "
                "{%0,%1,%2,%3},{%4,%5,%6,%7},{%8,%9},{%0,%1,%2,%3};"
                : "+f"(acc[t][0]), "+f"(acc[t][1]), "+f"(acc[t][2]), "+f"(acc[t][3])
                : "r"(ah0), "r"(ah1), "r"(ah2), "r"(ah3), "r"(bl0), "r"(bl1));
        }
    }

    int n0 = node0 + row0;
    int n1 = node0 + row1;
    #pragma unroll
    for (int t = 0; t < 8; t++) {
        int col = t * 8 + 2 * r;
        if (n0 < N)
            *(__half2*)(g_h1h + (size_t)n0 * HID + col) = __floats2half2_rn(acc[t][0], acc[t][1]);
        if (n1 < N)
            *(__half2*)(g_h1h + (size_t)n1 * HID + col) = __floats2half2_rn(acc[t][2], acc[t][3]);
    }
}

// ---------------- agg1 + gemm2 fused ----------------------------------------
// 8 warps = 8 nodes per block. Each warp: gather-sum layer-1, relu -> smem.
// Then 128 threads do the 8x64 @ 64x16 matvec and write fp16 h2s.
__global__ __launch_bounds__(256) void k_agg1f(const float* __restrict__ b1,
                                               const float* __restrict__ W2, int N) {
    __shared__ float xs[8][HID];     // relu outputs for 8 nodes
    __shared__ float W2s[HID * CLS]; // 4 KB
    __shared__ float dd[8];

    const int tid  = threadIdx.x;
    const int warp = tid >> 5;
    const int lane = tid & 31;
    const int node = blockIdx.x * 8 + warp;

    // stage W2 early (overlaps gather latency)
    for (int i = tid; i < HID * CLS; i += 256) W2s[i] = W2[i];

    if (node < N) {
        int rs = g_rowstart[node], re = g_rowstart[node + 1];
        float dw = g_dinv[node];

        float2 self = __half22float2(((const __half2*)(g_h1h + (size_t)node * HID))[lane]);
        float2 acc = make_float2(dw * self.x, dw * self.y);

        for (int base = rs; base < re; base += 32) {
            int n = re - base;
            int2 ed = make_int2(0, 0);
            if (lane < n) ed = g_edge[base + lane];
            int cnt = n < 32 ? n : 32;
            int j = 0;
            for (; j + 8 <= cnt; j += 8) {
                int   s0 = __shfl_sync(0xffffffffu, ed.x, j);
                int   s1 = __shfl_sync(0xffffffffu, ed.x, j + 1);
                int   s2 = __shfl_sync(0xffffffffu, ed.x, j + 2);
                int   s3 = __shfl_sync(0xffffffffu, ed.x, j + 3);
                int   s4 = __shfl_sync(0xffffffffu, ed.x, j + 4);
                int   s5 = __shfl_sync(0xffffffffu, ed.x, j + 5);
                int   s6 = __shfl_sync(0xffffffffu, ed.x, j + 6);
                int   s7 = __shfl_sync(0xffffffffu, ed.x, j + 7);
                float d0 = __int_as_float(__shfl_sync(0xffffffffu, ed.y, j));
                float d1 = __int_as_float(__shfl_sync(0xffffffffu, ed.y, j + 1));
                float d2 = __int_as_float(__shfl_sync(0xffffffffu, ed.y, j + 2));
                float d3 = __int_as_float(__shfl_sync(0xffffffffu, ed.y, j + 3));
                float d4 = __int_as_float(__shfl_sync(0xffffffffu, ed.y, j + 4));
                float d5 = __int_as_float(__shfl_sync(0xffffffffu, ed.y, j + 5));
                float d6 = __int_as_float(__shfl_sync(0xffffffffu, ed.y, j + 6));
                float d7 = __int_as_float(__shfl_sync(0xffffffffu, ed.y, j + 7));
                float2 v0 = __half22float2(((const __half2*)(g_h1h + (size_t)s0 * HID))[lane]);
                float2 v1 = __half22float2(((const __half2*)(g_h1h + (size_t)s1 * HID))[lane]);
                float2 v2 = __half22float2(((const __half2*)(g_h1h + (size_t)s2 * HID))[lane]);
                float2 v3 = __half22float2(((const __half2*)(g_h1h + (size_t)s3 * HID))[lane]);
                float2 v4 = __half22float2(((const __half2*)(g_h1h + (size_t)s4 * HID))[lane]);
                float2 v5 = __half22float2(((const __half2*)(g_h1h + (size_t)s5 * HID))[lane]);
                float2 v6 = __half22float2(((const __half2*)(g_h1h + (size_t)s6 * HID))[lane]);
                float2 v7 = __half22float2(((const __half2*)(g_h1h + (size_t)s7 * HID))[lane]);
                acc.x += d0 * v0.x + d1 * v1.x + d2 * v2.x + d3 * v3.x
                       + d4 * v4.x + d5 * v5.x + d6 * v6.x + d7 * v7.x;
                acc.y += d0 * v0.y + d1 * v1.y + d2 * v2.y + d3 * v3.y
                       + d4 * v4.y + d5 * v5.y + d6 * v6.y + d7 * v7.y;
            }
            for (; j < cnt; j++) {
                int s = __shfl_sync(0xffffffffu, ed.x, j);
                float d0 = __int_as_float(__shfl_sync(0xffffffffu, ed.y, j));
                float2 v = __half22float2(((const __half2*)(g_h1h + (size_t)s * HID))[lane]);
                acc.x += d0 * v.x; acc.y += d0 * v.y;
            }
        }

        float2 bb = ((const float2*)b1)[lane];
        xs[warp][2 * lane]     = fmaxf(fmaf(dw, acc.x, bb.x), 0.f);
        xs[warp][2 * lane + 1] = fmaxf(fmaf(dw, acc.y, bb.y), 0.f);
        if (lane == 0) dd[warp] = dw;
    }
    __syncthreads();

    // gemm2 part: 128 threads, thread t -> node t>>4, class t&15
    if (tid < 128) {
        int nn  = tid >> 4;
        int cls = tid & 15;
        int gnode = blockIdx.x * 8 + nn;
        if (gnode < N) {
            float a = 0.f;
            #pragma unroll 16
            for (int k = 0; k < HID; k++)
                a += xs[nn][k] * W2s[k * CLS + cls];
            g_h2sh[(size_t)gnode * CLS + cls] = __float2half_rn(a * dd[nn]);
        }
    }
}

// ---------------- agg2 + combine + log_softmax ------------------------------
__global__ __launch_bounds__(256) void k_agg2(const float* __restrict__ b2,
                                              float* __restrict__ out, int N) {
    int g = (blockIdx.x * 256 + threadIdx.x) >> 4;
    int lane = threadIdx.x & 15;
    int seg = (threadIdx.x >> 4) & 1;
    unsigned mask = 0xFFFFu << (seg * 16);
    if (g >= N) return;

    int rs = g_rowstart[g], re = g_rowstart[g + 1];
    float acc = __half2float(g_h2sh[(size_t)g * CLS + lane]);   // self term

    for (int base = rs; base < re; base += 16) {
        int n = re - base;
        int idx = (lane < n) ? g_edge[base + lane].x : 0;
        int cnt = n < 16 ? n : 16;
        int j = 0;
        for (; j + 4 <= cnt; j += 4) {
            int s0 = __shfl_sync(mask, idx, j, 16);
            int s1 = __shfl_sync(mask, idx, j + 1, 16);
            int s2 = __shfl_sync(mask, idx, j + 2, 16);
            int s3 = __shfl_sync(mask, idx, j + 3, 16);
            float v0 = __half2float(g_h2sh[(size_t)s0 * CLS + lane]);
            float v1 = __half2float(g_h2sh[(size_t)s1 * CLS + lane]);
            float v2 = __half2float(g_h2sh[(size_t)s2 * CLS + lane]);
            float v3 = __half2float(g_h2sh[(size_t)s3 * CLS + lane]);
            acc += v0 + v1 + v2 + v3;
        }
        for (; j < cnt; j++) {
            int s = __shfl_sync(mask, idx, j, 16);
            acc += __half2float(g_h2sh[(size_t)s * CLS + lane]);
        }
    }

    float d = g_dinv[g];
    float z = fmaxf(fmaf(d, acc, b2[lane]), 0.f);

    float m = z;
    #pragma unroll
    for (int off = 8; off; off >>= 1) m = fmaxf(m, __shfl_xor_sync(mask, m, off, 16));
    float e = expf(z - m);
    float ssum = e;
    #pragma unroll
    for (int off = 8; off; off >>= 1) ssum += __shfl_xor_sync(mask, ssum, off, 16);

    out[(size_t)g * CLS + lane] = z - (m + logf(ssum));
}

// ---------------- launcher ---------------------------------------------------
extern "C" void kernel_launch(void* const* d_in, const int* in_sizes, int n_in,
                              void* d_out, int out_size) {
    const float* x  = (const float*)d_in[0];
    const int*   ei = (const int*)d_in[1];
    const float* W1 = (const float*)d_in[2];
    const float* b1 = (const float*)d_in[3];
    const float* W2 = (const float*)d_in[4];
    const float* b2 = (const float*)d_in[5];
    float* out = (float*)d_out;

    const int N = in_sizes[0] / FIN;       // 100000
    const int E = in_sizes[1] / 2;         // 1600000
    const int* src = ei;
    const int* dst = ei + E;
    const int nb = (N + 1023) / 1024;

    static cudaStream_t s2 = nullptr;
    static cudaEvent_t evFork = nullptr, evJoin = nullptr;
    static int init_done = 0;
    if (!init_done) {
        cudaFuncSetAttribute(k_gemm1, cudaFuncAttributeMaxDynamicSharedMemorySize, GEMM1_SMEM);
        cudaStreamCreateWithFlags(&s2, cudaStreamNonBlocking);
        cudaEventCreateWithFlags(&evFork, cudaEventDisableTiming);
        cudaEventCreateWithFlags(&evJoin, cudaEventDisableTiming);
        init_done = 1;
    }

    // Fork: gemm1 (x,W1 only) concurrent with the CSR build chain.
    cudaEventRecord(evFork, 0);
    cudaStreamWaitEvent(s2, evFork, 0);
    k_gemm1<<<(N + 63) / 64, 128, GEMM1_SMEM, s2>>>(x, W1, N);
    cudaEventRecord(evJoin, s2);

    // CSR build chain on the main (capture) stream.
    k_zero_deg<<<(N + 255) / 256, 256>>>(N);
    k_deg<<<(E + 255) / 256, 256>>>(dst, E);
    k_scanA<<<nb, 1024>>>(N);
    k_scanC<<<nb, 1024>>>(N, E, nb);
    k_reorder<<<(E + 255) / 256, 256>>>(src, dst, E);

    // Join: agg1f needs both h1 and the CSR.
    cudaStreamWaitEvent(0, evJoin, 0);

    k_agg1f<<<(N + 7) / 8, 256>>>(b1, W2, N);

    {
        long long units = (long long)N * 16;
        k_agg2<<<(unsigned)((units + 255) / 256), 256>>>(b2, out, N);
    }
}